// round 15
// baseline (speedup 1.0000x reference)
#include <cuda_runtime.h>

// Problem-fixed sizes (reference: N=100000, F_IN=512, F_OUT=2).
#define NMAX 100000
#define FOUT 2
#define FIN 512

// __device__ globals are zero-initialized at module load; every call restores
// them to zero before finishing (gemm epilogue re-zeros g_deg, head resets
// scalar + ticket), so each graph replay sees identical initial state.
__device__ __align__(16) float g_deg[NMAX];
__device__ __align__(16) float g_dis[NMAX];
__device__ __align__(16) float g_hs[NMAX * FOUT];  // (x@W) * dis (gather source)
__device__ __align__(16) float g_acc[NMAX * FOUT]; // self-loop + edge sums
__device__ float g_acc_scalar;
__device__ unsigned int g_ticket;

// ---------------------------------------------------------------------------
// K1: deg segment-sum alone (no GEMM co-runner): 4 edges/thread, evict-first
// streams, spread-address REDs to the L2-resident 400KB g_deg.
__global__ __launch_bounds__(256) void deg_kernel(
        const int* __restrict__ col, const float* __restrict__ w, int E) {
    int t = blockIdx.x * blockDim.x + threadIdx.x;
    int base = t * 4;
    if (base + 3 < E) {
        int4 c4 = __ldcs((const int4*)(col + base));
        float4 w4 = __ldcs((const float4*)(w + base));
        atomicAdd(&g_deg[c4.x], w4.x);
        atomicAdd(&g_deg[c4.y], w4.y);
        atomicAdd(&g_deg[c4.z], w4.z);
        atomicAdd(&g_deg[c4.w], w4.w);
    } else {
        for (int e = base; e < E; ++e) atomicAdd(&g_deg[col[e]], w[e]);
    }
}

// ---------------------------------------------------------------------------
// K2: GEMM alone (best-measured config: one warp per row, 4 independent
// LDG.128 evict-first, W staged in smem read as float4), with the former
// post_kernel folded into the epilogue: deg is final when this launches, so
// lane 0 computes dis = rsqrt(deg+1), writes hs = h*dis and acc = hs
// (self-loop term), and re-zeros g_deg for the next replay.
__global__ __launch_bounds__(256) void gemm_kernel(
        const float* __restrict__ x, const float* __restrict__ W, int n) {
    __shared__ __align__(16) float sW[FIN * FOUT];
    for (int i = threadIdx.x; i < FIN * FOUT; i += blockDim.x) sW[i] = W[i];
    __syncthreads();

    int warp = threadIdx.x >> 5;
    int lane = threadIdx.x & 31;
    int row = (int)blockIdx.x * (blockDim.x >> 5) + warp;
    if (row >= n) return;

    const float4* xr = (const float4*)(x + (size_t)row * FIN);
    const float4* sW4 = (const float4*)sW;

    float4 v0 = __ldcs(xr + lane);        // zero-reuse stream: evict-first
    float4 v1 = __ldcs(xr + lane + 32);
    float4 v2 = __ldcs(xr + lane + 64);
    float4 v3 = __ldcs(xr + lane + 96);

    float a0 = 0.f, a1 = 0.f;
#define ACCUM(v, q)                                                        \
    {                                                                      \
        float4 wa = sW4[2 * (q)];                                          \
        float4 wb = sW4[2 * (q) + 1];                                      \
        a0 += v.x * wa.x + v.y * wa.z + v.z * wb.x + v.w * wb.z;           \
        a1 += v.x * wa.y + v.y * wa.w + v.z * wb.y + v.w * wb.w;           \
    }
    ACCUM(v0, lane)
    ACCUM(v1, lane + 32)
    ACCUM(v2, lane + 64)
    ACCUM(v3, lane + 96)
#undef ACCUM

#pragma unroll
    for (int off = 16; off; off >>= 1) {
        a0 += __shfl_down_sync(0xffffffffu, a0, off);
        a1 += __shfl_down_sync(0xffffffffu, a1, off);
    }
    if (lane == 0) {
        float d = g_deg[row] + 1.0f;  // self-loop weight; deg final here
        g_deg[row] = 0.0f;            // restore initial state for next call
        float dis = rsqrtf(d);        // d >= 1 always
        g_dis[row] = dis;
        float2 hs = make_float2(a0 * dis, a1 * dis);
        *(float2*)(g_hs + 2 * row) = hs;
        *(float2*)(g_acc + 2 * row) = hs;   // self-loop contribution
    }
}

// ---------------------------------------------------------------------------
// K3: edge scatter: acc[col] += hs[row] * w. One random 8B gather + one v2
// RED per edge; 4 edges/thread for gather ILP; edge-list streams use
// evict-first so L2 stays reserved for the hs/acc working sets.
__global__ __launch_bounds__(256) void edge_kernel(
        const int* __restrict__ row, const int* __restrict__ col,
        const float* __restrict__ w, int E) {
    int t = blockIdx.x * blockDim.x + threadIdx.x;
    int base = t * 4;
    if (base + 3 < E) {
        int4 r4 = __ldcs((const int4*)(row + base));
        int4 c4 = __ldcs((const int4*)(col + base));
        float4 w4 = __ldcs((const float4*)(w + base));
        float2 h0 = __ldg((const float2*)(g_hs + 2 * r4.x));
        float2 h1 = __ldg((const float2*)(g_hs + 2 * r4.y));
        float2 h2 = __ldg((const float2*)(g_hs + 2 * r4.z));
        float2 h3 = __ldg((const float2*)(g_hs + 2 * r4.w));
        asm volatile("red.global.add.v2.f32 [%0], {%1, %2};" ::
                     "l"(g_acc + 2 * c4.x), "f"(h0.x * w4.x), "f"(h0.y * w4.x) : "memory");
        asm volatile("red.global.add.v2.f32 [%0], {%1, %2};" ::
                     "l"(g_acc + 2 * c4.y), "f"(h1.x * w4.y), "f"(h1.y * w4.y) : "memory");
        asm volatile("red.global.add.v2.f32 [%0], {%1, %2};" ::
                     "l"(g_acc + 2 * c4.z), "f"(h2.x * w4.z), "f"(h2.y * w4.z) : "memory");
        asm volatile("red.global.add.v2.f32 [%0], {%1, %2};" ::
                     "l"(g_acc + 2 * c4.w), "f"(h3.x * w4.w), "f"(h3.y * w4.w) : "memory");
    } else {
        for (int e = base; e < E; ++e) {
            int r = row[e], c = col[e];
            float ww = w[e];
            float2 hv = __ldg((const float2*)(g_hs + 2 * r));
            asm volatile("red.global.add.v2.f32 [%0], {%1, %2};" ::
                         "l"(g_acc + 2 * c), "f"(hv.x * ww), "f"(hv.y * ww) : "memory");
        }
    }
}

// ---------------------------------------------------------------------------
// K4: head (+ fused final): each thread handles ONE float4 = 2 nodes
// (vectorized acc/fcw reads): p = sum relu(dis*acc + b) * fcw. Block-reduce
// into g_acc_scalar; ticketed last block applies sigmoid and resets state.
__global__ __launch_bounds__(512) void head_kernel(
        const float* __restrict__ bvec, const float* __restrict__ fcw,
        const float* __restrict__ fcb, float* __restrict__ out,
        int nq, int nblocks) {          // nq = n2/4 (float4 count)
    int i = blockIdx.x * blockDim.x + threadIdx.x;
    float p = 0.f;
    float b0 = bvec[0], b1 = bvec[1];
    if (i < nq) {
        float4 a4 = *(const float4*)(g_acc + 4 * i);   // nodes 2i, 2i+1
        float4 f4 = __ldcs((const float4*)(fcw + 4 * i));
        float2 d2 = *(const float2*)(g_dis + 2 * i);
        p = fmaxf(d2.x * a4.x + b0, 0.f) * f4.x +
            fmaxf(d2.x * a4.y + b1, 0.f) * f4.y +
            fmaxf(d2.y * a4.z + b0, 0.f) * f4.z +
            fmaxf(d2.y * a4.w + b1, 0.f) * f4.w;
    }
#pragma unroll
    for (int off = 16; off; off >>= 1) p += __shfl_down_sync(0xffffffffu, p, off);
    __shared__ float ws[16];
    __shared__ bool is_last;
    int lane = threadIdx.x & 31, wid = threadIdx.x >> 5;
    if (lane == 0) ws[wid] = p;
    __syncthreads();
    if (wid == 0) {
        p = (lane < (blockDim.x >> 5)) ? ws[lane] : 0.f;
#pragma unroll
        for (int off = 8; off; off >>= 1) p += __shfl_down_sync(0xffffffffu, p, off);
        if (lane == 0) {
            atomicAdd(&g_acc_scalar, p);
            __threadfence();
            unsigned int t = atomicAdd(&g_ticket, 1u);
            is_last = (t == (unsigned int)(nblocks - 1));
        }
    }
    __syncthreads();
    if (is_last && threadIdx.x == 0) {
        float l = g_acc_scalar + fcb[0];
        out[0] = 1.f / (1.f + expf(-l));
        g_acc_scalar = 0.0f;   // restore initial state for next call
        g_ticket = 0u;
    }
}

// ---------------------------------------------------------------------------
extern "C" void kernel_launch(void* const* d_in, const int* in_sizes, int n_in,
                              void* d_out, int out_size) {
    const float* x   = (const float*)d_in[0];      // [N, F_IN]
    const int*   el  = (const int*)d_in[1];        // [2, E] int32 (JAX downcast)
    const float* ea  = (const float*)d_in[2];      // [E]
    const float* W   = (const float*)d_in[3];      // [F_IN, 2]
    const float* b   = (const float*)d_in[4];      // [2]
    const float* fcw = (const float*)d_in[5];      // [2N]
    const float* fcb = (const float*)d_in[6];      // scalar

    int E  = in_sizes[2];
    int n2 = in_sizes[5];
    int n  = n2 / FOUT;

    const int* rowp = el;
    const int* colp = el + E;

    int gemmB = (n + 7) / 8;        // 8 warps -> 8 rows per block
    int nq    = n2 / 4;             // n2 % 4 == 0 (n even)
    int headB = (nq + 511) / 512;

    deg_kernel<<<(E / 4 + 255) / 256, 256>>>(colp, ea, E);
    gemm_kernel<<<gemmB, 256>>>(x, W, n);
    edge_kernel<<<(E / 4 + 255) / 256, 256>>>(rowp, colp, ea, E);
    head_kernel<<<headB, 512>>>(b, fcw, fcb, (float*)d_out, nq, headB);
}

// round 16
// speedup vs baseline: 2.4066x; 2.4066x over previous
#include <cuda_runtime.h>

// Problem-fixed sizes (reference: N=100000, F_IN=512, F_OUT=2).
#define NMAX 100000
#define FOUT 2
#define FIN 512

// __device__ globals are zero-initialized at module load; every call restores
// them to zero before finishing (post re-zeros g_deg, head resets scalar +
// ticket), so each graph replay sees identical initial state.
__device__ __align__(16) float g_deg[NMAX];
__device__ __align__(16) float g_dis[NMAX];
__device__ __align__(16) float g_h[NMAX * FOUT];   // x @ W
__device__ __align__(16) float g_hs[NMAX * FOUT];  // h * dis (gather source)
__device__ __align__(16) float g_acc[NMAX * FOUT]; // self-loop + edge sums
__device__ float g_acc_scalar;
__device__ unsigned int g_ticket;

// ---------------------------------------------------------------------------
// K1 (fused, best-measured config — R14): blocks [0, gemmB) compute h = x @ W
// (one warp per row, 4 independent LDG.128 with evict-first hint, W staged
// in smem read as float4); blocks [gemmB, gemmB+degB) do the deg segment-sum
// atomics and overlap with the GEMM's tail waves. This overlap is
// load-bearing: splitting deg into its own launch measured +133us (R15).
__global__ __launch_bounds__(256) void fused_gemm_deg(
        const float* __restrict__ x, const float* __restrict__ W, int n,
        int gemmB, const int* __restrict__ col, const float* __restrict__ w,
        int E) {
    if ((int)blockIdx.x >= gemmB) {
        // --- deg atomics: 4 edges/thread, streaming (evict-first) reads ---
        int t = ((int)blockIdx.x - gemmB) * blockDim.x + threadIdx.x;
        int base = t * 4;
        if (base + 3 < E) {
            int4 c4 = __ldcs((const int4*)(col + base));
            float4 w4 = __ldcs((const float4*)(w + base));
            atomicAdd(&g_deg[c4.x], w4.x);
            atomicAdd(&g_deg[c4.y], w4.y);
            atomicAdd(&g_deg[c4.z], w4.z);
            atomicAdd(&g_deg[c4.w], w4.w);
        } else {
            for (int e = base; e < E; ++e) atomicAdd(&g_deg[col[e]], w[e]);
        }
        return;
    }
    // --- GEMM: one warp per row; 4 independent LDG.128 cover the 2KB row ---
    __shared__ __align__(16) float sW[FIN * FOUT];
    for (int i = threadIdx.x; i < FIN * FOUT; i += blockDim.x) sW[i] = W[i];
    __syncthreads();

    int warp = threadIdx.x >> 5;
    int lane = threadIdx.x & 31;
    int row = (int)blockIdx.x * (blockDim.x >> 5) + warp;
    if (row >= n) return;

    const float4* xr = (const float4*)(x + (size_t)row * FIN);
    const float4* sW4 = (const float4*)sW;

    float4 v0 = __ldcs(xr + lane);        // zero-reuse stream: evict-first
    float4 v1 = __ldcs(xr + lane + 32);
    float4 v2 = __ldcs(xr + lane + 64);
    float4 v3 = __ldcs(xr + lane + 96);

    float a0 = 0.f, a1 = 0.f;
#define ACCUM(v, q)                                                        \
    {                                                                      \
        float4 wa = sW4[2 * (q)];                                          \
        float4 wb = sW4[2 * (q) + 1];                                      \
        a0 += v.x * wa.x + v.y * wa.z + v.z * wb.x + v.w * wb.z;           \
        a1 += v.x * wa.y + v.y * wa.w + v.z * wb.y + v.w * wb.w;           \
    }
    ACCUM(v0, lane)
    ACCUM(v1, lane + 32)
    ACCUM(v2, lane + 64)
    ACCUM(v3, lane + 96)
#undef ACCUM

#pragma unroll
    for (int off = 16; off; off >>= 1) {
        a0 += __shfl_down_sync(0xffffffffu, a0, off);
        a1 += __shfl_down_sync(0xffffffffu, a1, off);
    }
    if (lane == 0) {
        g_h[2 * row + 0] = a0;
        g_h[2 * row + 1] = a1;
    }
}

// ---------------------------------------------------------------------------
// K2: vectorized post (2 nodes/thread): dis = rsqrt(deg + 1); hs = h*dis;
// acc = hs (self-loop, weight 1); re-zero g_deg for the next replay.
__global__ void post_kernel(int nh) {   // nh = n/2
    int i = blockIdx.x * blockDim.x + threadIdx.x;
    if (i >= nh) return;
    float2 d2 = *(const float2*)(g_deg + 2 * i);
    *(float2*)(g_deg + 2 * i) = make_float2(0.f, 0.f);  // restore for next call
    float dis0 = rsqrtf(d2.x + 1.0f);   // self-loop weight; d >= 0
    float dis1 = rsqrtf(d2.y + 1.0f);
    *(float2*)(g_dis + 2 * i) = make_float2(dis0, dis1);
    float4 h4 = *(const float4*)(g_h + 4 * i);          // nodes 2i, 2i+1
    float4 hs4 = make_float4(h4.x * dis0, h4.y * dis0, h4.z * dis1, h4.w * dis1);
    *(float4*)(g_hs + 4 * i) = hs4;
    *(float4*)(g_acc + 4 * i) = hs4;
}

// ---------------------------------------------------------------------------
// K3: edge scatter: acc[col] += hs[row] * w. One random 8B gather + one v2
// RED per edge; 4 edges/thread for gather ILP; edge-list streams use
// evict-first so L2 stays reserved for the hs/acc working sets.
__global__ __launch_bounds__(256) void edge_kernel(
        const int* __restrict__ row, const int* __restrict__ col,
        const float* __restrict__ w, int E) {
    int t = blockIdx.x * blockDim.x + threadIdx.x;
    int base = t * 4;
    if (base + 3 < E) {
        int4 r4 = __ldcs((const int4*)(row + base));
        int4 c4 = __ldcs((const int4*)(col + base));
        float4 w4 = __ldcs((const float4*)(w + base));
        float2 h0 = __ldg((const float2*)(g_hs + 2 * r4.x));
        float2 h1 = __ldg((const float2*)(g_hs + 2 * r4.y));
        float2 h2 = __ldg((const float2*)(g_hs + 2 * r4.z));
        float2 h3 = __ldg((const float2*)(g_hs + 2 * r4.w));
        asm volatile("red.global.add.v2.f32 [%0], {%1, %2};" ::
                     "l"(g_acc + 2 * c4.x), "f"(h0.x * w4.x), "f"(h0.y * w4.x) : "memory");
        asm volatile("red.global.add.v2.f32 [%0], {%1, %2};" ::
                     "l"(g_acc + 2 * c4.y), "f"(h1.x * w4.y), "f"(h1.y * w4.y) : "memory");
        asm volatile("red.global.add.v2.f32 [%0], {%1, %2};" ::
                     "l"(g_acc + 2 * c4.z), "f"(h2.x * w4.z), "f"(h2.y * w4.z) : "memory");
        asm volatile("red.global.add.v2.f32 [%0], {%1, %2};" ::
                     "l"(g_acc + 2 * c4.w), "f"(h3.x * w4.w), "f"(h3.y * w4.w) : "memory");
    } else {
        for (int e = base; e < E; ++e) {
            int r = row[e], c = col[e];
            float ww = w[e];
            float2 hv = __ldg((const float2*)(g_hs + 2 * r));
            asm volatile("red.global.add.v2.f32 [%0], {%1, %2};" ::
                         "l"(g_acc + 2 * c), "f"(hv.x * ww), "f"(hv.y * ww) : "memory");
        }
    }
}

// ---------------------------------------------------------------------------
// K4: head (+ fused final): each thread handles ONE float4 = 2 nodes
// (vectorized acc/fcw reads): p = sum relu(dis*acc + b) * fcw. Block-reduce
// into g_acc_scalar; ticketed last block applies sigmoid and resets state.
__global__ __launch_bounds__(512) void head_kernel(
        const float* __restrict__ bvec, const float* __restrict__ fcw,
        const float* __restrict__ fcb, float* __restrict__ out,
        int nq, int nblocks) {          // nq = n2/4 (float4 count)
    int i = blockIdx.x * blockDim.x + threadIdx.x;
    float p = 0.f;
    float b0 = bvec[0], b1 = bvec[1];
    if (i < nq) {
        float4 a4 = *(const float4*)(g_acc + 4 * i);   // nodes 2i, 2i+1
        float4 f4 = __ldcs((const float4*)(fcw + 4 * i));
        float2 d2 = *(const float2*)(g_dis + 2 * i);
        p = fmaxf(d2.x * a4.x + b0, 0.f) * f4.x +
            fmaxf(d2.x * a4.y + b1, 0.f) * f4.y +
            fmaxf(d2.y * a4.z + b0, 0.f) * f4.z +
            fmaxf(d2.y * a4.w + b1, 0.f) * f4.w;
    }
#pragma unroll
    for (int off = 16; off; off >>= 1) p += __shfl_down_sync(0xffffffffu, p, off);
    __shared__ float ws[16];
    __shared__ bool is_last;
    int lane = threadIdx.x & 31, wid = threadIdx.x >> 5;
    if (lane == 0) ws[wid] = p;
    __syncthreads();
    if (wid == 0) {
        p = (lane < (blockDim.x >> 5)) ? ws[lane] : 0.f;
#pragma unroll
        for (int off = 8; off; off >>= 1) p += __shfl_down_sync(0xffffffffu, p, off);
        if (lane == 0) {
            atomicAdd(&g_acc_scalar, p);
            __threadfence();
            unsigned int t = atomicAdd(&g_ticket, 1u);
            is_last = (t == (unsigned int)(nblocks - 1));
        }
    }
    __syncthreads();
    if (is_last && threadIdx.x == 0) {
        float l = g_acc_scalar + fcb[0];
        out[0] = 1.f / (1.f + expf(-l));
        g_acc_scalar = 0.0f;   // restore initial state for next call
        g_ticket = 0u;
    }
}

// ---------------------------------------------------------------------------
extern "C" void kernel_launch(void* const* d_in, const int* in_sizes, int n_in,
                              void* d_out, int out_size) {
    const float* x   = (const float*)d_in[0];      // [N, F_IN]
    const int*   el  = (const int*)d_in[1];        // [2, E] int32 (JAX downcast)
    const float* ea  = (const float*)d_in[2];      // [E]
    const float* W   = (const float*)d_in[3];      // [F_IN, 2]
    const float* b   = (const float*)d_in[4];      // [2]
    const float* fcw = (const float*)d_in[5];      // [2N]
    const float* fcb = (const float*)d_in[6];      // scalar

    int E  = in_sizes[2];
    int n2 = in_sizes[5];
    int n  = n2 / FOUT;

    const int* rowp = el;
    const int* colp = el + E;

    int gemmB = (n + 7) / 8;        // 8 warps -> 8 rows per block
    int degB  = (E + 1023) / 1024;  // 256 thr * 4 edges per block
    int nh    = n / 2;              // n even
    int nq    = n2 / 4;             // n2 % 4 == 0
    int headB = (nq + 511) / 512;

    fused_gemm_deg<<<gemmB + degB, 256>>>(x, W, n, gemmB, colp, ea, E);
    post_kernel<<<(nh + 255) / 256, 256>>>(nh);
    edge_kernel<<<(E / 4 + 255) / 256, 256>>>(rowp, colp, ea, E);
    head_kernel<<<headB, 512>>>(b, fcw, fcb, (float*)d_out, nq, headB);
}